// round 2
// baseline (speedup 1.0000x reference)
#include <cuda_runtime.h>
#include <cuda_fp16.h>
#include <cstdint>

#define N_ROWS 16384
#define DIMS   128
#define BM     128
#define BN     128
#define LDT    136   // padded smem row stride in halves (272B): 16B-aligned, conflict-free gathers

// Scratch (allocation-free rule: device globals)
__device__ __half g_A[N_ROWS * DIMS];
__device__ __half g_B[N_ROWS * DIMS];
__device__ int    g_lab[N_ROWS];
__device__ int    g_lab64_flag;
__device__ double g_acc;

// ---------------------------------------------------------------------------
// Kernel 1: L2-normalize rows of both inputs, write fp16
// ---------------------------------------------------------------------------
__global__ void normalize_kernel(const float* __restrict__ a,
                                 const float* __restrict__ b) {
    int row = blockIdx.x;
    const float* src;
    __half* dst;
    if (row < N_ROWS) { src = a + (size_t)row * DIMS; dst = g_A + (size_t)row * DIMS; }
    else { row -= N_ROWS; src = b + (size_t)row * DIMS; dst = g_B + (size_t)row * DIMS; }

    int t = threadIdx.x;
    float v = src[t];
    float ss = v * v;
#pragma unroll
    for (int o = 16; o; o >>= 1) ss += __shfl_xor_sync(0xffffffffu, ss, o);
    __shared__ float ws[4];
    if ((t & 31) == 0) ws[t >> 5] = ss;
    __syncthreads();
    float tot = ws[0] + ws[1] + ws[2] + ws[3];
    float inv = 1.0f / fmaxf(sqrtf(tot), 1e-12f);
    dst[t] = __float2half(v * inv);
}

// ---------------------------------------------------------------------------
// Kernel 2a: detect whether the label buffer is int64 or int32.
// Reads the first 8192 int64 (= 64KB, in-bounds for either dtype).
// Labels are in [0,100); int32-pairs read as int64 are >= 2^32 w.h.p.
// ---------------------------------------------------------------------------
__global__ void label_detect_kernel(const long long* __restrict__ lab) {
    int i = blockIdx.x * blockDim.x + threadIdx.x;
    if (i == 0) { g_lab64_flag = 1; g_acc = 0.0; }
    __threadfence();
    if (i < 8192) {
        long long v = lab[i];
        if (v < 0 || v >= 1000000) atomicExch(&g_lab64_flag, 0);
    }
}

// Kernel 2b: convert labels to int32 per detected dtype.
__global__ void label_convert_kernel(const void* __restrict__ lab) {
    int i = blockIdx.x * blockDim.x + threadIdx.x;
    if (i < N_ROWS) {
        if (g_lab64_flag) g_lab[i] = (int)((const long long*)lab)[i];
        else              g_lab[i] = ((const int*)lab)[i];
    }
}

// ---------------------------------------------------------------------------
// Kernel 3: fused GEMM (fp16 mma.sync m16n8k16, fp32 accum) + exp/mask/sum.
// CTA tile 128x128, K=128 resident. 256 threads = 8 warps (4x2), each warp
// computes a 32x64 sub-tile. Fragments gathered with explicit LDS.32 per the
// PTX ISA fragment tables (no ldmatrix — unambiguous layout).
// ---------------------------------------------------------------------------
__global__ void __launch_bounds__(256, 2) gemm_loss_kernel() {
    extern __shared__ char smem_raw[];
    __half* As = (__half*)smem_raw;                 // [BM][LDT]
    __half* Bs = As + BM * LDT;                     // [BN][LDT]
    int* labA = (int*)(Bs + BN * LDT);              // [128]
    int* labB = labA + 128;                         // [128]

    const int tid   = threadIdx.x;
    const int rowA0 = blockIdx.y * BM;
    const int rowB0 = blockIdx.x * BN;

    // ---- stage tiles: 2048 uint4 per tile, 8 per thread ----
    const uint4* gA = (const uint4*)(g_A + (size_t)rowA0 * DIMS);
    const uint4* gB = (const uint4*)(g_B + (size_t)rowB0 * DIMS);
#pragma unroll
    for (int it = 0; it < 8; it++) {
        int c  = it * 256 + tid;
        int r  = c >> 4;
        int cc = c & 15;
        *(uint4*)(As + r * LDT + cc * 8) = gA[r * 16 + cc];
        *(uint4*)(Bs + r * LDT + cc * 8) = gB[r * 16 + cc];
    }
    if (tid < 128) labA[tid] = g_lab[rowA0 + tid];
    else           labB[tid - 128] = g_lab[rowB0 + tid - 128];
    __syncthreads();

    const int wid  = tid >> 5;
    const int lane = tid & 31;
    const int wm   = wid >> 1;           // 0..3: 32-row group
    const int wn   = wid & 1;            // 0..1: 64-col group
    const int grp  = lane >> 2;          // 0..7
    const int tig  = lane & 3;           // 0..3

    float acc[2][8][4];
#pragma unroll
    for (int mi = 0; mi < 2; mi++)
#pragma unroll
        for (int ni = 0; ni < 8; ni++)
#pragma unroll
            for (int q = 0; q < 4; q++) acc[mi][ni][q] = 0.f;

#pragma unroll
    for (int kk = 0; kk < DIMS; kk += 16) {
        const int koff = kk + 2 * tig;

        // A fragments: per PTX ISA m16n8k16 table.
        // reg0: (row grp,    k=2*tig)   reg1: (row grp+8,  k=2*tig)
        // reg2: (row grp,    k+8)       reg3: (row grp+8,  k+8)
        uint32_t af[2][4];
#pragma unroll
        for (int mi = 0; mi < 2; mi++) {
            const __half* base = As + (wm * 32 + mi * 16 + grp) * LDT + koff;
            af[mi][0] = *(const uint32_t*)(base);
            af[mi][1] = *(const uint32_t*)(base + 8 * LDT);
            af[mi][2] = *(const uint32_t*)(base + 8);
            af[mi][3] = *(const uint32_t*)(base + 8 * LDT + 8);
        }
        // B fragments: reg0: (n=grp, k=2*tig), reg1: (n=grp, k+8).
        // Storage is [n][k] with k contiguous — direct gather.
        uint32_t bf[8][2];
#pragma unroll
        for (int ni = 0; ni < 8; ni++) {
            const __half* base = Bs + (wn * 64 + ni * 8 + grp) * LDT + koff;
            bf[ni][0] = *(const uint32_t*)(base);
            bf[ni][1] = *(const uint32_t*)(base + 8);
        }
#pragma unroll
        for (int mi = 0; mi < 2; mi++) {
#pragma unroll
            for (int ni = 0; ni < 8; ni++) {
                asm volatile(
                    "mma.sync.aligned.m16n8k16.row.col.f32.f16.f16.f32 "
                    "{%0,%1,%2,%3}, {%4,%5,%6,%7}, {%8,%9}, {%0,%1,%2,%3};"
                    : "+f"(acc[mi][ni][0]), "+f"(acc[mi][ni][1]),
                      "+f"(acc[mi][ni][2]), "+f"(acc[mi][ni][3])
                    : "r"(af[mi][0]), "r"(af[mi][1]), "r"(af[mi][2]), "r"(af[mi][3]),
                      "r"(bf[ni][0]), "r"(bf[ni][1]));
            }
        }
    }

    // ---- epilogue: exp(-2*sim) masked by label difference ----
    // C fragment: c0,c1 at (row grp, col 2*tig + {0,1}); c2,c3 at row grp+8.
    float local = 0.f;
    const int r0 = wm * 32 + grp;
    const int c0 = wn * 64 + 2 * tig;
#pragma unroll
    for (int mi = 0; mi < 2; mi++) {
#pragma unroll
        for (int ni = 0; ni < 8; ni++) {
            int rr = r0 + mi * 16;
            int cc = c0 + ni * 8;
            int la0 = labA[rr], la1 = labA[rr + 8];
            int lb0 = labB[cc], lb1 = labB[cc + 1];
            local += (la0 != lb0) ? __expf(-2.f * acc[mi][ni][0]) : 0.f;
            local += (la0 != lb1) ? __expf(-2.f * acc[mi][ni][1]) : 0.f;
            local += (la1 != lb0) ? __expf(-2.f * acc[mi][ni][2]) : 0.f;
            local += (la1 != lb1) ? __expf(-2.f * acc[mi][ni][3]) : 0.f;
        }
    }

#pragma unroll
    for (int o = 16; o; o >>= 1) local += __shfl_xor_sync(0xffffffffu, local, o);
    __shared__ float wsum[8];
    if (lane == 0) wsum[wid] = local;
    __syncthreads();
    if (tid == 0) {
        float s = 0.f;
#pragma unroll
        for (int w = 0; w < 8; w++) s += wsum[w];
        atomicAdd(&g_acc, (double)s);
    }
}

// ---------------------------------------------------------------------------
// Kernel 4: finalize scalar
// ---------------------------------------------------------------------------
__global__ void finalize_kernel(float* __restrict__ out) {
    out[0] = (float)(g_acc / ((double)N_ROWS * (double)(N_ROWS - 1)));
}

extern "C" void kernel_launch(void* const* d_in, const int* in_sizes, int n_in,
                              void* d_out, int out_size) {
    const float* a   = (const float*)d_in[0];
    const float* b   = (const float*)d_in[1];
    const void*  lab = d_in[2];
    float* out = (float*)d_out;

    normalize_kernel<<<2 * N_ROWS, DIMS>>>(a, b);
    label_detect_kernel<<<(8192 + 255) / 256, 256>>>((const long long*)lab);
    label_convert_kernel<<<(N_ROWS + 255) / 256, 256>>>(lab);

    const int smem_bytes = (BM + BN) * LDT * (int)sizeof(__half) + 256 * (int)sizeof(int);
    cudaFuncSetAttribute(gemm_loss_kernel,
                         cudaFuncAttributeMaxDynamicSharedMemorySize, smem_bytes);
    dim3 grid(N_ROWS / BN, N_ROWS / BM);
    gemm_loss_kernel<<<grid, 256, smem_bytes>>>();

    finalize_kernel<<<1, 1>>>(out);
}

// round 4
// speedup vs baseline: 1.0177x; 1.0177x over previous
#include <cuda_runtime.h>
#include <cstdint>

#define N_ROWS 16384
#define DIMS   128          // bytes per row in fp8
#define SROW   192          // padded smem row stride (bytes); 192/16=12 ≡ 4 mod 8 -> conflict-free
#define SM_A    0
#define SM_B    24576       // 128 * 192
#define SM_LABA 49152
#define SM_LABB 49664
#define SM_RED  50176
#define SM_TOT  50240

// Scratch (allocation-free rule: device globals). Rows are chunk-permuted fp8.
__device__ unsigned char g_A[N_ROWS * DIMS];
__device__ unsigned char g_B[N_ROWS * DIMS];
__device__ int    g_lab[N_ROWS];
__device__ int    g_lab64_flag;
__device__ double g_acc;

// ---------------------------------------------------------------------------
// Kernel 1: L2-normalize rows, convert to e4m3, store chunk-permuted.
// One warp per row; lane handles quad q = lane (k = 4q..4q+3).
// Permutation: quad q -> word index (4*(q>>4) + (q&3))*4 + ((q>>2)&3).
// This puts all quads a given mma-lane needs into contiguous 16B chunks.
// ---------------------------------------------------------------------------
__global__ void normalize_kernel(const float* __restrict__ a,
                                 const float* __restrict__ b) {
    int w    = (blockIdx.x * blockDim.x + threadIdx.x) >> 5;
    int lane = threadIdx.x & 31;
    if (w >= 2 * N_ROWS) return;
    const float* src;
    unsigned char* dst;
    if (w < N_ROWS) { src = a + (size_t)w * 128; dst = g_A + (size_t)w * DIMS; }
    else { src = b + (size_t)(w - N_ROWS) * 128; dst = g_B + (size_t)(w - N_ROWS) * DIMS; }

    float4 v = ((const float4*)src)[lane];
    float ss = v.x * v.x + v.y * v.y + v.z * v.z + v.w * v.w;
#pragma unroll
    for (int o = 16; o; o >>= 1) ss += __shfl_xor_sync(0xffffffffu, ss, o);
    float inv = rsqrtf(fmaxf(ss, 1e-24f));
    float x0 = v.x * inv, x1 = v.y * inv, x2 = v.z * inv, x3 = v.w * inv;

    unsigned short p01, p23;  // cvt packs: low byte <- second operand
    asm("cvt.rn.satfinite.e4m3x2.f32 %0, %1, %2;" : "=h"(p01) : "f"(x1), "f"(x0));
    asm("cvt.rn.satfinite.e4m3x2.f32 %0, %1, %2;" : "=h"(p23) : "f"(x3), "f"(x2));
    uint32_t word = (uint32_t)p01 | ((uint32_t)p23 << 16);

    int wpos = (4 * (lane >> 4) + (lane & 3)) * 4 + ((lane >> 2) & 3);
    ((uint32_t*)dst)[wpos] = word;
}

// ---------------------------------------------------------------------------
// Kernel 2a/2b: label dtype detection (int64 vs int32) + conversion
// ---------------------------------------------------------------------------
__global__ void label_detect_kernel(const long long* __restrict__ lab) {
    int i = blockIdx.x * blockDim.x + threadIdx.x;
    if (i == 0) { g_lab64_flag = 1; g_acc = 0.0; }
    __threadfence();
    if (i < 8192) {
        long long v = lab[i];
        if (v < 0 || v >= 1000000) atomicExch(&g_lab64_flag, 0);
    }
}
__global__ void label_convert_kernel(const void* __restrict__ lab) {
    int i = blockIdx.x * blockDim.x + threadIdx.x;
    if (i < N_ROWS) {
        if (g_lab64_flag) g_lab[i] = (int)((const long long*)lab)[i];
        else              g_lab[i] = ((const int*)lab)[i];
    }
}

// ---------------------------------------------------------------------------
// Kernel 3: fused fp8 GEMM (mma.sync m16n8k32 e4m3, f32 acc) + exp/mask/sum.
// CTA tile 128x128, K=128. 256 threads = 8 warps (4x2), warp tile 32x64.
// Fragments loaded as LDS.128 from the chunk-permuted layout:
//   chunk (t, tig) of a row holds quads k = 4*tig + 16*(4t+u), u=0..3
//   -> words [2s], [2s+1] of chunk t are the (a0/b0, a2/b1) quads for
//      k-step kk = 64t + 32s.
// ---------------------------------------------------------------------------
__global__ void __launch_bounds__(256, 2) gemm_loss_kernel() {
    extern __shared__ char sm[];
    char* smA = sm + SM_A;
    char* smB = sm + SM_B;
    int*  labA = (int*)(sm + SM_LABA);
    int*  labB = (int*)(sm + SM_LABB);

    const int tid   = threadIdx.x;
    const int rowA0 = blockIdx.y * 128;
    const int rowB0 = blockIdx.x * 128;

    // ---- stage tiles: 1024 16B-chunks each, straight copy (permutation is in gmem) ----
    const uint4* gA = (const uint4*)(g_A + (size_t)rowA0 * DIMS);
    const uint4* gB = (const uint4*)(g_B + (size_t)rowB0 * DIMS);
#pragma unroll
    for (int i = 0; i < 4; i++) {
        int idx = i * 256 + tid;           // 0..1023
        int r = idx >> 3, c = idx & 7;
        *(uint4*)(smA + r * SROW + c * 16) = gA[r * 8 + c];
        *(uint4*)(smB + r * SROW + c * 16) = gB[r * 8 + c];
    }
    if (tid < 128) labA[tid] = g_lab[rowA0 + tid];
    else           labB[tid - 128] = g_lab[rowB0 + tid - 128];
    __syncthreads();

    const int wid  = tid >> 5;
    const int lane = tid & 31;
    const int wm   = wid >> 1;          // 0..3
    const int wn   = wid & 1;           // 0..1
    const int grp  = lane >> 2;         // 0..7
    const int tig  = lane & 3;          // 0..3

    float acc[2][8][4];
#pragma unroll
    for (int mi = 0; mi < 2; mi++)
#pragma unroll
        for (int ni = 0; ni < 8; ni++)
#pragma unroll
            for (int q = 0; q < 4; q++) acc[mi][ni][q] = 0.f;

    const char* aP = smA + (wm * 32 + grp) * SROW + tig * 16;
    const char* bP = smB + (wn * 64 + grp) * SROW + tig * 16;

#pragma unroll
    for (int t = 0; t < 2; t++) {
        // A fragments: rows grp+{0,8,16,24} within the warp's 32-row band
        uint32_t A_w[4][4];
#pragma unroll
        for (int rh = 0; rh < 4; rh++) {
            uint4 u = *(const uint4*)(aP + rh * 8 * SROW + t * 64);
            A_w[rh][0] = u.x; A_w[rh][1] = u.y; A_w[rh][2] = u.z; A_w[rh][3] = u.w;
        }
        // B fragments: rows (n) grp + 8*ni within the warp's 64-col band
        uint32_t B_w[8][4];
#pragma unroll
        for (int ni = 0; ni < 8; ni++) {
            uint4 u = *(const uint4*)(bP + ni * 8 * SROW + t * 64);
            B_w[ni][0] = u.x; B_w[ni][1] = u.y; B_w[ni][2] = u.z; B_w[ni][3] = u.w;
        }
#pragma unroll
        for (int s = 0; s < 2; s++) {      // k-step kk = 64t + 32s
#pragma unroll
            for (int mi = 0; mi < 2; mi++) {
                uint32_t a0 = A_w[2 * mi][2 * s];
                uint32_t a1 = A_w[2 * mi + 1][2 * s];
                uint32_t a2 = A_w[2 * mi][2 * s + 1];
                uint32_t a3 = A_w[2 * mi + 1][2 * s + 1];
#pragma unroll
                for (int ni = 0; ni < 8; ni++) {
                    asm volatile(
                        "mma.sync.aligned.m16n8k32.row.col.f32.e4m3.e4m3.f32 "
                        "{%0,%1,%2,%3}, {%4,%5,%6,%7}, {%8,%9}, {%0,%1,%2,%3};"
                        : "+f"(acc[mi][ni][0]), "+f"(acc[mi][ni][1]),
                          "+f"(acc[mi][ni][2]), "+f"(acc[mi][ni][3])
                        : "r"(a0), "r"(a1), "r"(a2), "r"(a3),
                          "r"(B_w[ni][2 * s]), "r"(B_w[ni][2 * s + 1]));
                }
            }
        }
    }

    // ---- epilogue: exp(-2*sim) masked by label difference ----
    float local = 0.f;
    const int r0 = wm * 32 + grp;
    const int c0 = wn * 64 + 2 * tig;
#pragma unroll
    for (int mi = 0; mi < 2; mi++) {
#pragma unroll
        for (int ni = 0; ni < 8; ni++) {
            int rr = r0 + mi * 16;
            int cc = c0 + ni * 8;
            int la0 = labA[rr], la1 = labA[rr + 8];
            int lb0 = labB[cc], lb1 = labB[cc + 1];
            local += (la0 != lb0) ? __expf(-2.f * acc[mi][ni][0]) : 0.f;
            local += (la0 != lb1) ? __expf(-2.f * acc[mi][ni][1]) : 0.f;
            local += (la1 != lb0) ? __expf(-2.f * acc[mi][ni][2]) : 0.f;
            local += (la1 != lb1) ? __expf(-2.f * acc[mi][ni][3]) : 0.f;
        }
    }

#pragma unroll
    for (int o = 16; o; o >>= 1) local += __shfl_xor_sync(0xffffffffu, local, o);
    float* red = (float*)(sm + SM_RED);
    if (lane == 0) red[wid] = local;
    __syncthreads();
    if (tid == 0) {
        float s = 0.f;
#pragma unroll
        for (int w = 0; w < 8; w++) s += red[w];
        atomicAdd(&g_acc, (double)s);
    }
}

// ---------------------------------------------------------------------------
// Kernel 4: finalize scalar
// ---------------------------------------------------------------------------
__global__ void finalize_kernel(float* __restrict__ out) {
    out[0] = (float)(g_acc / ((double)N_ROWS * (double)(N_ROWS - 1)));
}

extern "C" void kernel_launch(void* const* d_in, const int* in_sizes, int n_in,
                              void* d_out, int out_size) {
    const float* a   = (const float*)d_in[0];
    const float* b   = (const float*)d_in[1];
    const void*  lab = d_in[2];
    float* out = (float*)d_out;

    normalize_kernel<<<(2 * N_ROWS * 32) / 256, 256>>>(a, b);
    label_detect_kernel<<<(8192 + 255) / 256, 256>>>((const long long*)lab);
    label_convert_kernel<<<(N_ROWS + 255) / 256, 256>>>(lab);

    cudaFuncSetAttribute(gemm_loss_kernel,
                         cudaFuncAttributeMaxDynamicSharedMemorySize, SM_TOT);
    dim3 grid(N_ROWS / 128, N_ROWS / 128);
    gemm_loss_kernel<<<grid, 256, SM_TOT>>>();

    finalize_kernel<<<1, 1>>>(out);
}

// round 5
// speedup vs baseline: 1.1716x; 1.1512x over previous
#include <cuda_runtime.h>
#include <cuda_fp16.h>
#include <cstdint>

#define N_ROWS 16384
#define DIMS   128          // bytes per row in fp8
#define SROW   192          // padded smem row stride (bytes); conflict-free for LDS.128 frag gathers
#define SM_A    0
#define SM_B    24576       // 128 * 192
#define SM_LABA 49152       // 128 half
#define SM_LABB 49408       // 128 half
#define SM_RED  49664       // 16 floats
#define SM_TOT  49728

// exp(-sim/0.5) = 2^(sim * -2*log2(e)); fold the scale into B at quantize time.
#define BSCALE (-2.8853900817779268f)

// Scratch (allocation-free rule: device globals). Rows are chunk-permuted fp8.
__device__ unsigned char g_A[N_ROWS * DIMS];
__device__ unsigned char g_B[N_ROWS * DIMS];
__device__ __half g_labh[N_ROWS];
__device__ int    g_lab64_flag;
__device__ double g_acc;

// ---------------------------------------------------------------------------
// Kernel 1: L2-normalize rows, convert to e4m3, store chunk-permuted.
// One warp per row; lane handles quad q = lane (k = 4q..4q+3).
// B rows additionally scaled by BSCALE (folds temperature + log2e into GEMM).
// ---------------------------------------------------------------------------
__global__ void normalize_kernel(const float* __restrict__ a,
                                 const float* __restrict__ b) {
    int w    = (blockIdx.x * blockDim.x + threadIdx.x) >> 5;
    int lane = threadIdx.x & 31;
    if (w >= 2 * N_ROWS) return;
    const float* src;
    unsigned char* dst;
    float extra;
    if (w < N_ROWS) { src = a + (size_t)w * 128; dst = g_A + (size_t)w * DIMS; extra = 1.f; }
    else { src = b + (size_t)(w - N_ROWS) * 128; dst = g_B + (size_t)(w - N_ROWS) * DIMS; extra = BSCALE; }

    float4 v = ((const float4*)src)[lane];
    float ss = v.x * v.x + v.y * v.y + v.z * v.z + v.w * v.w;
#pragma unroll
    for (int o = 16; o; o >>= 1) ss += __shfl_xor_sync(0xffffffffu, ss, o);
    float inv = rsqrtf(fmaxf(ss, 1e-24f)) * extra;
    float x0 = v.x * inv, x1 = v.y * inv, x2 = v.z * inv, x3 = v.w * inv;

    unsigned short p01, p23;  // cvt packs: low byte <- second operand
    asm("cvt.rn.satfinite.e4m3x2.f32 %0, %1, %2;" : "=h"(p01) : "f"(x1), "f"(x0));
    asm("cvt.rn.satfinite.e4m3x2.f32 %0, %1, %2;" : "=h"(p23) : "f"(x3), "f"(x2));
    uint32_t word = (uint32_t)p01 | ((uint32_t)p23 << 16);

    int wpos = (4 * (lane >> 4) + (lane & 3)) * 4 + ((lane >> 2) & 3);
    ((uint32_t*)dst)[wpos] = word;
}

// ---------------------------------------------------------------------------
// Kernel 2a/2b: label dtype detection (int64 vs int32) + conversion to half
// (labels < 100 are exact in fp16; compares done in fp16 pipe in the epilogue)
// ---------------------------------------------------------------------------
__global__ void label_detect_kernel(const long long* __restrict__ lab) {
    int i = blockIdx.x * blockDim.x + threadIdx.x;
    if (i == 0) { g_lab64_flag = 1; g_acc = 0.0; }
    __threadfence();
    if (i < 8192) {
        long long v = lab[i];
        if (v < 0 || v >= 1000000) atomicExch(&g_lab64_flag, 0);
    }
}
__global__ void label_convert_kernel(const void* __restrict__ lab) {
    int i = blockIdx.x * blockDim.x + threadIdx.x;
    if (i < N_ROWS) {
        int l;
        if (g_lab64_flag) l = (int)((const long long*)lab)[i];
        else              l = ((const int*)lab)[i];
        g_labh[i] = __int2half_rn(l);
    }
}

// ---------------------------------------------------------------------------
// Kernel 3: fused fp8 GEMM (mma.sync m16n8k32 e4m3, f32 acc) + exp2/mask/sum.
// CTA tile 128x128, K=128. 512 threads = 16 warps (4x4), warp tile 32x32.
// acc = -2*log2(e)*sim directly (B pre-scaled) -> epilogue = h2exp2 + hne2 + hfma2.
// ---------------------------------------------------------------------------
__global__ void __launch_bounds__(512, 2) gemm_loss_kernel() {
    extern __shared__ char sm[];
    char* smA = sm + SM_A;
    char* smB = sm + SM_B;
    __half* labA = (__half*)(sm + SM_LABA);
    __half* labB = (__half*)(sm + SM_LABB);

    const int tid   = threadIdx.x;
    const int rowA0 = blockIdx.y * 128;
    const int rowB0 = blockIdx.x * 128;

    // ---- stage tiles: 1024 uint4 per tile, 2 per thread per tile ----
    const uint4* gA = (const uint4*)(g_A + (size_t)rowA0 * DIMS);
    const uint4* gB = (const uint4*)(g_B + (size_t)rowB0 * DIMS);
#pragma unroll
    for (int i = 0; i < 2; i++) {
        int idx = i * 512 + tid;           // 0..1023
        int r = idx >> 3, c = idx & 7;
        *(uint4*)(smA + r * SROW + c * 16) = gA[r * 8 + c];
        *(uint4*)(smB + r * SROW + c * 16) = gB[r * 8 + c];
    }
    if (tid < 128) labA[tid] = g_labh[rowA0 + tid];
    else if (tid < 256) labB[tid - 128] = g_labh[rowB0 + tid - 128];
    __syncthreads();

    const int wid  = tid >> 5;
    const int lane = tid & 31;
    const int wm   = wid >> 2;          // 0..3: 32-row band
    const int wn   = wid & 3;           // 0..3: 32-col band
    const int grp  = lane >> 2;         // 0..7
    const int tig  = lane & 3;          // 0..3

    float acc[2][4][4];
#pragma unroll
    for (int mi = 0; mi < 2; mi++)
#pragma unroll
        for (int ni = 0; ni < 4; ni++)
#pragma unroll
            for (int q = 0; q < 4; q++) acc[mi][ni][q] = 0.f;

    const char* aP = smA + (wm * 32 + grp) * SROW + tig * 16;
    const char* bP = smB + (wn * 32 + grp) * SROW + tig * 16;

#pragma unroll
    for (int t = 0; t < 2; t++) {
        // A fragments: rows grp+{0,8,16,24} within the warp's 32-row band
        uint32_t A_w[4][4];
#pragma unroll
        for (int rh = 0; rh < 4; rh++) {
            uint4 u = *(const uint4*)(aP + rh * 8 * SROW + t * 64);
            A_w[rh][0] = u.x; A_w[rh][1] = u.y; A_w[rh][2] = u.z; A_w[rh][3] = u.w;
        }
#pragma unroll
        for (int ni = 0; ni < 4; ni++) {
            uint4 bu = *(const uint4*)(bP + ni * 8 * SROW + t * 64);
            uint32_t B_w[4] = {bu.x, bu.y, bu.z, bu.w};
#pragma unroll
            for (int s = 0; s < 2; s++) {
#pragma unroll
                for (int mi = 0; mi < 2; mi++) {
                    asm volatile(
                        "mma.sync.aligned.m16n8k32.row.col.f32.e4m3.e4m3.f32 "
                        "{%0,%1,%2,%3}, {%4,%5,%6,%7}, {%8,%9}, {%0,%1,%2,%3};"
                        : "+f"(acc[mi][ni][0]), "+f"(acc[mi][ni][1]),
                          "+f"(acc[mi][ni][2]), "+f"(acc[mi][ni][3])
                        : "r"(A_w[2 * mi][2 * s]), "r"(A_w[2 * mi + 1][2 * s]),
                          "r"(A_w[2 * mi][2 * s + 1]), "r"(A_w[2 * mi + 1][2 * s + 1]),
                          "r"(B_w[2 * s]), "r"(B_w[2 * s + 1]));
                }
            }
        }
    }

    // ---- epilogue: sum 2^acc over label-differing pairs, f16x2 path ----
    const int r0 = wm * 32 + grp;
    const int c0 = wn * 32 + 2 * tig;
    __half2 la2[4];                    // rows r0, r0+8, r0+16, r0+24 broadcast
#pragma unroll
    for (int j = 0; j < 4; j++) la2[j] = __half2half2(labA[r0 + 8 * j]);
    __half2 lb2[4];                    // col pairs (c, c+1) per ni
#pragma unroll
    for (int ni = 0; ni < 4; ni++) lb2[ni] = *(const __half2*)&labB[c0 + ni * 8];

    __half2 tsum = __float2half2_rn(0.f);
#pragma unroll
    for (int mi = 0; mi < 2; mi++) {
#pragma unroll
        for (int ni = 0; ni < 4; ni++) {
            __half2 h0 = __floats2half2_rn(acc[mi][ni][0], acc[mi][ni][1]);
            __half2 h1 = __floats2half2_rn(acc[mi][ni][2], acc[mi][ni][3]);
            __half2 e0 = h2exp2(h0);
            __half2 e1 = h2exp2(h1);
            __half2 m0 = __hne2(la2[2 * mi], lb2[ni]);
            __half2 m1 = __hne2(la2[2 * mi + 1], lb2[ni]);
            tsum = __hfma2(e0, m0, tsum);
            tsum = __hfma2(e1, m1, tsum);
        }
    }
    float local = __low2float(tsum) + __high2float(tsum);

#pragma unroll
    for (int o = 16; o; o >>= 1) local += __shfl_xor_sync(0xffffffffu, local, o);
    float* red = (float*)(sm + SM_RED);
    if (lane == 0) red[wid] = local;
    __syncthreads();
    if (tid == 0) {
        float s = 0.f;
#pragma unroll
        for (int w = 0; w < 16; w++) s += red[w];
        atomicAdd(&g_acc, (double)s);
    }
}

// ---------------------------------------------------------------------------
// Kernel 4: finalize scalar
// ---------------------------------------------------------------------------
__global__ void finalize_kernel(float* __restrict__ out) {
    out[0] = (float)(g_acc / ((double)N_ROWS * (double)(N_ROWS - 1)));
}

extern "C" void kernel_launch(void* const* d_in, const int* in_sizes, int n_in,
                              void* d_out, int out_size) {
    const float* a   = (const float*)d_in[0];
    const float* b   = (const float*)d_in[1];
    const void*  lab = d_in[2];
    float* out = (float*)d_out;

    normalize_kernel<<<(2 * N_ROWS * 32) / 256, 256>>>(a, b);
    label_detect_kernel<<<(8192 + 255) / 256, 256>>>((const long long*)lab);
    label_convert_kernel<<<(N_ROWS + 255) / 256, 256>>>(lab);

    cudaFuncSetAttribute(gemm_loss_kernel,
                         cudaFuncAttributeMaxDynamicSharedMemorySize, SM_TOT);
    dim3 grid(N_ROWS / 128, N_ROWS / 128);
    gemm_loss_kernel<<<grid, 512, SM_TOT>>>();

    finalize_kernel<<<1, 1>>>(out);
}

// round 6
// speedup vs baseline: 1.3593x; 1.1602x over previous
#include <cuda_runtime.h>
#include <cuda_fp16.h>
#include <cstdint>

#define N_ROWS 16384
#define DIMS   128          // bytes per row in fp8
#define SROW   192          // padded smem row stride (bytes); conflict-free LDS.128 frag gathers
#define SEGS   16
#define TPS    (128 / SEGS) // tiles per CTA (bx per segment)

#define SMB0     0
#define SMB1     24576      // 128 * 192
#define SM_LABB0 49152      // 128 half = 256B
#define SM_LABB1 49408
#define SM_RED   49664      // 16 floats
#define SM_TOT   49728

// exp(-sim/0.5) = 2^(sim * -2*log2(e)); fold scale into B at quantize time.
#define BSCALE (-2.8853900817779268f)

#define CP16(dst_u32, src_ptr) \
    asm volatile("cp.async.cg.shared.global [%0], [%1], 16;" :: "r"(dst_u32), "l"(src_ptr))

// Scratch (allocation-free rule: device globals). Rows are chunk-permuted fp8.
__device__ unsigned char g_A[N_ROWS * DIMS];
__device__ unsigned char g_B[N_ROWS * DIMS];
__device__ __half g_labh[N_ROWS];
__device__ int    g_lab64_flag;
__device__ double g_acc;

// ---------------------------------------------------------------------------
// Kernel 1: L2-normalize rows, convert to e4m3, store chunk-permuted.
// One warp per row; lane handles quad q = lane (k = 4q..4q+3).
// B rows additionally scaled by BSCALE (folds temperature + log2e into GEMM).
// ---------------------------------------------------------------------------
__global__ void normalize_kernel(const float* __restrict__ a,
                                 const float* __restrict__ b) {
    int w    = (blockIdx.x * blockDim.x + threadIdx.x) >> 5;
    int lane = threadIdx.x & 31;
    if (w >= 2 * N_ROWS) return;
    const float* src;
    unsigned char* dst;
    float extra;
    if (w < N_ROWS) { src = a + (size_t)w * 128; dst = g_A + (size_t)w * DIMS; extra = 1.f; }
    else { src = b + (size_t)(w - N_ROWS) * 128; dst = g_B + (size_t)(w - N_ROWS) * DIMS; extra = BSCALE; }

    float4 v = ((const float4*)src)[lane];
    float ss = v.x * v.x + v.y * v.y + v.z * v.z + v.w * v.w;
#pragma unroll
    for (int o = 16; o; o >>= 1) ss += __shfl_xor_sync(0xffffffffu, ss, o);
    float inv = rsqrtf(fmaxf(ss, 1e-24f)) * extra;
    float x0 = v.x * inv, x1 = v.y * inv, x2 = v.z * inv, x3 = v.w * inv;

    unsigned short p01, p23;  // cvt packs: low byte <- second operand
    asm("cvt.rn.satfinite.e4m3x2.f32 %0, %1, %2;" : "=h"(p01) : "f"(x1), "f"(x0));
    asm("cvt.rn.satfinite.e4m3x2.f32 %0, %1, %2;" : "=h"(p23) : "f"(x3), "f"(x2));
    uint32_t word = (uint32_t)p01 | ((uint32_t)p23 << 16);

    int wpos = (4 * (lane >> 4) + (lane & 3)) * 4 + ((lane >> 2) & 3);
    ((uint32_t*)dst)[wpos] = word;
}

// ---------------------------------------------------------------------------
// Kernel 2a/2b: label dtype detection (int64 vs int32) + conversion to half
// ---------------------------------------------------------------------------
__global__ void label_detect_kernel(const long long* __restrict__ lab) {
    int i = blockIdx.x * blockDim.x + threadIdx.x;
    if (i == 0) { g_lab64_flag = 1; g_acc = 0.0; }
    __threadfence();
    if (i < 8192) {
        long long v = lab[i];
        if (v < 0 || v >= 1000000) atomicExch(&g_lab64_flag, 0);
    }
}
__global__ void label_convert_kernel(const void* __restrict__ lab) {
    int i = blockIdx.x * blockDim.x + threadIdx.x;
    if (i < N_ROWS) {
        int l;
        if (g_lab64_flag) l = (int)((const long long*)lab)[i];
        else              l = ((const int*)lab)[i];
        g_labh[i] = __int2half_rn(l);
    }
}

// ---------------------------------------------------------------------------
// Kernel 3: row-persistent fused fp8 GEMM + exp2/mask/sum.
// Each CTA: fixed 128-row band (by), TPS consecutive 128-col tiles.
// A fragments (full K=128) cached in registers for the whole CTA lifetime,
// loaded directly from the chunk-permuted gmem. B double-buffered via
// cp.async. 512 threads = 16 warps (4x4), warp tile 32x32.
// ---------------------------------------------------------------------------
__global__ void __launch_bounds__(512, 1) gemm_loss_kernel() {
    extern __shared__ char sm[];
    uint32_t sb = (uint32_t)__cvta_generic_to_shared(sm);
    const int tid  = threadIdx.x;
    const int wid  = tid >> 5;
    const int lane = tid & 31;
    const int wm   = wid >> 2;          // 0..3: 32-row band
    const int wn   = wid & 3;           // 0..3: 32-col band
    const int grp  = lane >> 2;         // 0..7
    const int tig  = lane & 3;          // 0..3

    const int by  = blockIdx.x & 127;
    const int seg = blockIdx.x >> 7;
    const int bx0 = seg * TPS;

    // ---- cache A fragments for this thread's rows, full K=128 (32 regs) ----
    uint4 Af[2][4];
#pragma unroll
    for (int rh = 0; rh < 4; rh++)
#pragma unroll
        for (int t = 0; t < 2; t++)
            Af[t][rh] = *(const uint4*)(g_A +
                (size_t)(by * 128 + wm * 32 + grp + 8 * rh) * DIMS + t * 64 + tig * 16);

    const int r0 = wm * 32 + grp;
    __half2 la2[4];
#pragma unroll
    for (int j = 0; j < 4; j++) la2[j] = __half2half2(g_labh[by * 128 + r0 + 8 * j]);

    // ---- prefetch first B tile into buffer 0 ----
    {
        const char* gB = (const char*)g_B + (size_t)(bx0 * 128) * DIMS;
        int r = tid >> 3, c = tid & 7;
        CP16(sb + SMB0 + r * SROW + c * 16, gB + tid * 16);
        int i2 = tid + 512; r = i2 >> 3; c = i2 & 7;
        CP16(sb + SMB0 + r * SROW + c * 16, gB + i2 * 16);
        if (tid < 16)
            CP16(sb + SM_LABB0 + tid * 16, (const char*)(g_labh + bx0 * 128) + tid * 16);
        asm volatile("cp.async.commit_group;" ::: "memory");
    }

    float local = 0.f;
    for (int i = 0; i < TPS; i++) {
        if (i + 1 < TPS) {
            const int bxn = bx0 + i + 1;
            const char* gB = (const char*)g_B + (size_t)(bxn * 128) * DIMS;
            const uint32_t dst  = sb + (((i + 1) & 1) ? SMB1 : SMB0);
            const uint32_t ldst = sb + (((i + 1) & 1) ? SM_LABB1 : SM_LABB0);
            int r = tid >> 3, c = tid & 7;
            CP16(dst + r * SROW + c * 16, gB + tid * 16);
            int i2 = tid + 512; r = i2 >> 3; c = i2 & 7;
            CP16(dst + r * SROW + c * 16, gB + i2 * 16);
            if (tid < 16)
                CP16(ldst + tid * 16, (const char*)(g_labh + bxn * 128) + tid * 16);
            asm volatile("cp.async.commit_group;" ::: "memory");
            asm volatile("cp.async.wait_group 1;" ::: "memory");
        } else {
            asm volatile("cp.async.wait_group 0;" ::: "memory");
        }
        __syncthreads();

        const char*   smB  = sm + ((i & 1) ? SMB1 : SMB0);
        const __half* labB = (const __half*)(sm + ((i & 1) ? SM_LABB1 : SM_LABB0));

        float acc[2][4][4];
#pragma unroll
        for (int mi = 0; mi < 2; mi++)
#pragma unroll
            for (int ni = 0; ni < 4; ni++)
#pragma unroll
                for (int q = 0; q < 4; q++) acc[mi][ni][q] = 0.f;

        const char* bP = smB + (wn * 32 + grp) * SROW + tig * 16;
#pragma unroll
        for (int t = 0; t < 2; t++) {
#pragma unroll
            for (int ni = 0; ni < 4; ni++) {
                uint4 bu = *(const uint4*)(bP + ni * 8 * SROW + t * 64);
                const uint32_t* B_w = (const uint32_t*)&bu;
#pragma unroll
                for (int s = 0; s < 2; s++) {
#pragma unroll
                    for (int mi = 0; mi < 2; mi++) {
                        const uint32_t* A0 = (const uint32_t*)&Af[t][2 * mi];
                        const uint32_t* A1 = (const uint32_t*)&Af[t][2 * mi + 1];
                        asm volatile(
                            "mma.sync.aligned.m16n8k32.row.col.f32.e4m3.e4m3.f32 "
                            "{%0,%1,%2,%3}, {%4,%5,%6,%7}, {%8,%9}, {%0,%1,%2,%3};"
                            : "+f"(acc[mi][ni][0]), "+f"(acc[mi][ni][1]),
                              "+f"(acc[mi][ni][2]), "+f"(acc[mi][ni][3])
                            : "r"(A0[2 * s]), "r"(A1[2 * s]),
                              "r"(A0[2 * s + 1]), "r"(A1[2 * s + 1]),
                              "r"(B_w[2 * s]), "r"(B_w[2 * s + 1]));
                    }
                }
            }
        }

        // ---- epilogue: sum 2^acc over label-differing pairs (f16x2 path) ----
        const int c0 = wn * 32 + 2 * tig;
        __half2 tsum = __float2half2_rn(0.f);
#pragma unroll
        for (int mi = 0; mi < 2; mi++) {
#pragma unroll
            for (int ni = 0; ni < 4; ni++) {
                __half2 lb2 = *(const __half2*)&labB[c0 + ni * 8];
                __half2 h0 = __floats2half2_rn(acc[mi][ni][0], acc[mi][ni][1]);
                __half2 h1 = __floats2half2_rn(acc[mi][ni][2], acc[mi][ni][3]);
                __half2 e0 = h2exp2(h0);
                __half2 e1 = h2exp2(h1);
                __half2 m0 = __hne2(la2[2 * mi], lb2);
                __half2 m1 = __hne2(la2[2 * mi + 1], lb2);
                tsum = __hfma2(e0, m0, tsum);
                tsum = __hfma2(e1, m1, tsum);
            }
        }
        local += __low2float(tsum) + __high2float(tsum);
        __syncthreads();   // all reads of this buffer done before next prefetch overwrites it
    }

    // ---- block reduction + single atomic ----
#pragma unroll
    for (int o = 16; o; o >>= 1) local += __shfl_xor_sync(0xffffffffu, local, o);
    float* red = (float*)(sm + SM_RED);
    if (lane == 0) red[wid] = local;
    __syncthreads();
    if (tid == 0) {
        float s = 0.f;
#pragma unroll
        for (int w = 0; w < 16; w++) s += red[w];
        atomicAdd(&g_acc, (double)s);
    }
}

// ---------------------------------------------------------------------------
// Kernel 4: finalize scalar
// ---------------------------------------------------------------------------
__global__ void finalize_kernel(float* __restrict__ out) {
    out[0] = (float)(g_acc / ((double)N_ROWS * (double)(N_ROWS - 1)));
}

extern "C" void kernel_launch(void* const* d_in, const int* in_sizes, int n_in,
                              void* d_out, int out_size) {
    const float* a   = (const float*)d_in[0];
    const float* b   = (const float*)d_in[1];
    const void*  lab = d_in[2];
    float* out = (float*)d_out;

    normalize_kernel<<<(2 * N_ROWS * 32) / 256, 256>>>(a, b);
    label_detect_kernel<<<(8192 + 255) / 256, 256>>>((const long long*)lab);
    label_convert_kernel<<<(N_ROWS + 255) / 256, 256>>>(lab);

    cudaFuncSetAttribute(gemm_loss_kernel,
                         cudaFuncAttributeMaxDynamicSharedMemorySize, SM_TOT);
    gemm_loss_kernel<<<128 * SEGS, 512, SM_TOT>>>();

    finalize_kernel<<<1, 1>>>(out);
}